// round 11
// baseline (speedup 1.0000x reference)
#include <cuda_runtime.h>
#include <cuda_bf16.h>
#include <math.h>

// VQ-VAE fwd fp32 NCHW. Output: out | z_e | e_k | ids (float32 concat)
#define B 8
#define OUT_N   (8*3*128*128)
#define ZE_OFF  OUT_N
#define ZE_N    (8*64*32*32)
#define EK_OFF  (ZE_OFF + ZE_N)
#define IDS_OFF (EK_OFF + ZE_N)

typedef unsigned long long u64;
#define FMA2(d, a, b) asm("fma.rn.f32x2 %0, %1, %2, %0;" : "+l"(d) : "l"(a), "l"(b))
__device__ __forceinline__ float2 unpack2(u64 v) {
    float2 r; asm("mov.b64 {%0, %1}, %2;" : "=f"(r.x), "=f"(r.y) : "l"(v)); return r;
}
__device__ __forceinline__ void cpa16(unsigned s, const float4* g) {
    asm volatile("cp.async.ca.shared.global [%0], [%1], 16;" :: "r"(s), "l"(g));
}
#define CPA_COMMIT() asm volatile("cp.async.commit_group;" ::: "memory")
#define CPA_WAIT0()  asm volatile("cp.async.wait_group 0;" ::: "memory")

__device__ float g_h1[8u*256u*64u*64u];
__device__ float g_h2[8u*256u*32u*32u];
__device__ float g_r [8u*256u*32u*32u];
__device__ float g_z [8u*64u*32u*32u];
__device__ float g_ek[8u*64u*32u*32u];
// k-split partial buffers
__device__ float g_p0 [8u*256u*32u*32u];
__device__ float g_p1 [8u*256u*32u*32u];
__device__ float g_rp0[8u*256u*32u*32u];
__device__ float g_rp1[8u*256u*32u*32u];

// transposed weight scratch (layouts linear in ic)
__device__ float g_wc2t[4u*64u*4096u];
__device__ float g_w3t0[4u*32u*4608u];
__device__ float g_w3t1[4u*32u*4608u];
__device__ float g_wt1t[8u*32u*4096u];

__global__ void k_dummy() {}

// ---------------- weight transposes (tiny) ----------------------------------
__global__ void tr3(const float* __restrict__ w, float* __restrict__ o_)
{
    int o = threadIdx.x, tap = threadIdx.y;
    int ic = blockIdx.x, obk = blockIdx.y;
    o_[(((size_t)obk*256 + ic)*9 + tap)*64 + o] =
        w[((size_t)(obk*64 + o)*256 + ic)*9 + tap];
}
__global__ void trc2(const float* __restrict__ w, float* __restrict__ o_)
{
    int o = threadIdx.x, tap = threadIdx.y;
    int chunk = blockIdx.x, obk = blockIdx.y;
    #pragma unroll
    for (int ci = 0; ci < 4; ci++)
        o_[(size_t)(obk*64 + chunk)*4096 + (ci*16 + tap)*64 + o] =
            w[((size_t)(obk*64 + o)*256 + chunk*4 + ci)*16 + tap];
}
__global__ void trt1(const float* __restrict__ w, float* __restrict__ o_)
{
    int o = threadIdx.x, tap = threadIdx.y;
    int chunk = blockIdx.x, obk = blockIdx.y;
    #pragma unroll
    for (int ci = 0; ci < 8; ci++)
        o_[(size_t)(obk*32 + chunk)*4096 + (ci*16 + tap)*32 + o] =
            w[((size_t)(chunk*8 + ci)*256 + obk*32 + o)*16 + tap];
}

// ---------------- c1: 3->256 k4 s2 p1, 128->64, relu (small) ----------------
__global__ void k_c1(const float* __restrict__ x, const float* __restrict__ w,
                     const float* __restrict__ bias)
{
    int b  = blockIdx.x >> 6;
    int oy = blockIdx.x & 63;
    int oc0 = blockIdx.y * 16;
    int tx = threadIdx.x, ty = threadIdx.y;
    int tid = ty * 64 + tx;

    __shared__ float s_in[3][4][130];
    __shared__ float s_w[16][48];

    for (int e = tid; e < 3*4*130; e += 256) {
        int c = e / 520, rem = e % 520;
        int ky = rem / 130, col = rem % 130;
        int iy = 2*oy - 1 + ky, ix = col - 1;
        float v = 0.f;
        if (iy >= 0 && iy < 128 && ix >= 0 && ix < 128)
            v = x[((b*3 + c)*128 + iy)*128 + ix];
        s_in[c][ky][col] = v;
    }
    for (int e = tid; e < 768; e += 256)
        s_w[e / 48][e % 48] = w[(oc0 + e/48)*48 + e%48];
    __syncthreads();

    float acc[4] = {0.f, 0.f, 0.f, 0.f};
    #pragma unroll
    for (int c = 0; c < 3; c++)
        #pragma unroll
        for (int ky = 0; ky < 4; ky++)
            #pragma unroll
            for (int kx = 0; kx < 4; kx++) {
                float v = s_in[c][ky][2*tx + kx];
                int r = (c*4 + ky)*4 + kx;
                #pragma unroll
                for (int j = 0; j < 4; j++) acc[j] += s_w[ty*4 + j][r] * v;
            }
    #pragma unroll
    for (int j = 0; j < 4; j++) {
        int oc = oc0 + ty*4 + j;
        g_h1[((size_t)(b*256 + oc)*64 + oy)*64 + tx] = fmaxf(acc[j] + bias[oc], 0.f);
    }
}

// ---------------- c2: k-split partial conv, 64->32 (f32x2, cp.async db) -----
// grid (64, 4, 2), block 128, 4 blocks/SM target.
__global__ void __launch_bounds__(128, 4) k_c2(const float* __restrict__ wT,
                                               const float* __restrict__ bias,
                                               float* __restrict__ o0,
                                               float* __restrict__ o1)
{
    int b   = blockIdx.x >> 3;
    int oy0 = (blockIdx.x & 7) * 4;
    int obk = blockIdx.y;
    int oc0 = obk * 64;
    int z   = blockIdx.z;
    int ic0 = z * 128;
    float* outb = z ? o1 : o0;
    int tid = threadIdx.x;
    int lane = tid & 31, warp = tid >> 5;
    int ocw = warp * 16;

    __shared__ __align__(16) float2 s_in[2][2][10][2][34];
    __shared__ __align__(16) float  s_w[2][2048];

    u64 acc[4][2][4] = {};

    const int cW = warp & 1;
    const int rB = (warp >> 1) * 5;

    #define C2_STAGE_IN(bf, c0) do {                                           \
        const float* rowb = &g_h1[(size_t)(b*256 + (c0) + cW)*4096];           \
        _Pragma("unroll")                                                      \
        for (int rr = 0; rr < 5; rr++) {                                       \
            int r = rB + rr;                                                   \
            int iy = 2*oy0 - 1 + r;                                            \
            bool yok = (iy >= 0 && iy < 64);                                   \
            const float* row = rowb + iy*64;                                   \
            int ix = lane - 1;                                                 \
            float v = (yok && ix >= 0) ? row[ix] : 0.f;                        \
            s_in[bf][cW][r][ix & 1][(ix + (ix & 1)) >> 1] = make_float2(v, v); \
            int ix2 = lane + 31;                                               \
            float v2 = yok ? row[ix2] : 0.f;                                   \
            s_in[bf][cW][r][ix2 & 1][(ix2 + (ix2 & 1)) >> 1] = make_float2(v2, v2); \
            if (lane < 2) {                                                    \
                int ix3 = lane + 63;                                           \
                float v3 = (yok && ix3 < 64) ? row[ix3] : 0.f;                 \
                s_in[bf][cW][r][ix3 & 1][(ix3 + (ix3 & 1)) >> 1] = make_float2(v3, v3); \
            }                                                                  \
        }                                                                      \
    } while (0)

    #define C2_STAGE_W(bf, c0) do {                                            \
        const float4* src = (const float4*)(wT + (size_t)obk*262144 + (size_t)(c0)*1024); \
        unsigned dst = (unsigned)__cvta_generic_to_shared(s_w[bf]);            \
        _Pragma("unroll")                                                      \
        for (int i = 0; i < 4; i++)                                            \
            cpa16(dst + (tid + 128*i)*16, src + tid + 128*i);                  \
    } while (0)

    C2_STAGE_W(0, ic0); CPA_COMMIT();
    C2_STAGE_IN(0, ic0);
    CPA_WAIT0();
    __syncthreads();

    int n = 0;
    for (int c0 = ic0; c0 < ic0 + 128; c0 += 2) {
        int nx = c0 + 2;
        if (nx < ic0 + 128) { C2_STAGE_W(n^1, nx); CPA_COMMIT(); C2_STAGE_IN(n^1, nx); }

        #pragma unroll
        for (int c = 0; c < 2; c++) {
            #pragma unroll
            for (int ky = 0; ky < 4; ky++) {
                #pragma unroll
                for (int kx = 0; kx < 4; kx++) {
                    int p = (kx & 1) ^ 1;
                    int j = lane + (kx >> 1);
                    u64 v0 = *(const u64*)&s_in[n][c][0 + ky][p][j];
                    u64 v1 = *(const u64*)&s_in[n][c][2 + ky][p][j];
                    u64 v2 = *(const u64*)&s_in[n][c][4 + ky][p][j];
                    u64 v3 = *(const u64*)&s_in[n][c][6 + ky][p][j];
                    const float* wrow = &s_w[n][(c*16 + ky*4 + kx)*64 + ocw];
                    #pragma unroll
                    for (int jj = 0; jj < 4; jj++) {
                        ulonglong2 wp = *(const ulonglong2*)&wrow[4*jj];
                        FMA2(acc[jj][0][0], wp.x, v0); FMA2(acc[jj][1][0], wp.y, v0);
                        FMA2(acc[jj][0][1], wp.x, v1); FMA2(acc[jj][1][1], wp.y, v1);
                        FMA2(acc[jj][0][2], wp.x, v2); FMA2(acc[jj][1][2], wp.y, v2);
                        FMA2(acc[jj][0][3], wp.x, v3); FMA2(acc[jj][1][3], wp.y, v3);
                    }
                }
            }
        }
        if (nx < ic0 + 128) CPA_WAIT0();
        __syncthreads();
        n ^= 1;
    }

    #pragma unroll
    for (int jj = 0; jj < 4; jj++)
        #pragma unroll
        for (int h = 0; h < 2; h++) {
            int oc = oc0 + ocw + 4*jj + 2*h;
            float b0 = z ? 0.f : bias[oc];
            float b1 = z ? 0.f : bias[oc + 1];
            #pragma unroll
            for (int py = 0; py < 4; py++) {
                float2 f = unpack2(acc[jj][h][py]);
                int oy = oy0 + py;
                outb[((size_t)(b*256 + oc    )*32 + oy)*32 + lane] = f.x + b0;
                outb[((size_t)(b*256 + oc + 1)*32 + oy)*32 + lane] = f.y + b1;
            }
        }
}

// ---------------- res3: k-split partial conv3x3 (f32x2, cp.async db) --------
template<int SUMIN>
__global__ void __launch_bounds__(128, 4) k_res3(const float* __restrict__ wT,
                                                 const float* __restrict__ bias,
                                                 const float* __restrict__ in0,
                                                 const float* __restrict__ in1,
                                                 float* __restrict__ o0,
                                                 float* __restrict__ o1)
{
    int b   = blockIdx.x >> 3;
    int oy0 = (blockIdx.x & 7) * 4;
    int obk = blockIdx.y;
    int oc0 = obk * 64;
    int z   = blockIdx.z;
    int ic0 = z * 128;
    float* outb = z ? o1 : o0;
    int tid = threadIdx.x;
    int lane = tid & 31, warp = tid >> 5;
    int ocw = warp * 16;

    __shared__ __align__(16) float2 s_in[2][4][6][34];
    __shared__ __align__(16) float  s_w[2][2304];

    u64 acc[4][2][4] = {};

    #define R3_STAGE_IN(bf, c0) do {                                           \
        size_t cb = (size_t)(b*256 + (c0) + warp)*1024;                        \
        _Pragma("unroll")                                                      \
        for (int r = 0; r < 6; r++) {                                          \
            int iy = oy0 - 1 + r;                                              \
            bool yok = (iy >= 0 && iy < 32);                                   \
            int ix = lane - 1;                                                 \
            float v = 0.f;                                                     \
            if (yok && ix >= 0) {                                              \
                v = in0[cb + iy*32 + ix];                                      \
                if (SUMIN) v += in1[cb + iy*32 + ix];                          \
                v = fmaxf(v, 0.f);                                             \
            }                                                                  \
            s_in[bf][warp][r][lane] = make_float2(v, v);                       \
            if (lane < 2) {                                                    \
                int ix2 = lane + 31;                                           \
                float v2 = 0.f;                                                \
                if (yok && ix2 < 32) {                                         \
                    v2 = in0[cb + iy*32 + ix2];                                \
                    if (SUMIN) v2 += in1[cb + iy*32 + ix2];                    \
                    v2 = fmaxf(v2, 0.f);                                       \
                }                                                              \
                s_in[bf][warp][r][lane + 32] = make_float2(v2, v2);            \
            }                                                                  \
        }                                                                      \
    } while (0)

    #define R3_STAGE_W(bf, c0) do {                                            \
        const float4* src = (const float4*)(wT + (size_t)obk*147456 + (size_t)(c0)*576); \
        unsigned dst = (unsigned)__cvta_generic_to_shared(s_w[bf]);            \
        _Pragma("unroll")                                                      \
        for (int i = 0; i < 4; i++)                                            \
            cpa16(dst + (tid + 128*i)*16, src + tid + 128*i);                  \
        if (tid < 64) cpa16(dst + (tid + 512)*16, src + tid + 512);            \
    } while (0)

    R3_STAGE_W(0, ic0); CPA_COMMIT();
    R3_STAGE_IN(0, ic0);
    CPA_WAIT0();
    __syncthreads();

    int n = 0;
    for (int c0 = ic0; c0 < ic0 + 128; c0 += 4) {
        int nx = c0 + 4;
        if (nx < ic0 + 128) { R3_STAGE_W(n^1, nx); CPA_COMMIT(); R3_STAGE_IN(n^1, nx); }

        #pragma unroll
        for (int c = 0; c < 4; c++) {
            #pragma unroll
            for (int ky = 0; ky < 3; ky++) {
                #pragma unroll
                for (int kx = 0; kx < 3; kx++) {
                    u64 v0 = *(const u64*)&s_in[n][c][0 + ky][lane + kx];
                    u64 v1 = *(const u64*)&s_in[n][c][1 + ky][lane + kx];
                    u64 v2 = *(const u64*)&s_in[n][c][2 + ky][lane + kx];
                    u64 v3 = *(const u64*)&s_in[n][c][3 + ky][lane + kx];
                    const float* wrow = &s_w[n][(c*9 + ky*3 + kx)*64 + ocw];
                    #pragma unroll
                    for (int jj = 0; jj < 4; jj++) {
                        ulonglong2 wp = *(const ulonglong2*)&wrow[4*jj];
                        FMA2(acc[jj][0][0], wp.x, v0); FMA2(acc[jj][1][0], wp.y, v0);
                        FMA2(acc[jj][0][1], wp.x, v1); FMA2(acc[jj][1][1], wp.y, v1);
                        FMA2(acc[jj][0][2], wp.x, v2); FMA2(acc[jj][1][2], wp.y, v2);
                        FMA2(acc[jj][0][3], wp.x, v3); FMA2(acc[jj][1][3], wp.y, v3);
                    }
                }
            }
        }
        if (nx < ic0 + 128) CPA_WAIT0();
        __syncthreads();
        n ^= 1;
    }

    #pragma unroll
    for (int jj = 0; jj < 4; jj++)
        #pragma unroll
        for (int h = 0; h < 2; h++) {
            int oc = oc0 + ocw + 4*jj + 2*h;
            float b0 = z ? 0.f : bias[oc];
            float b1 = z ? 0.f : bias[oc + 1];
            #pragma unroll
            for (int py = 0; py < 4; py++) {
                float2 f = unpack2(acc[jj][h][py]);
                int oy = oy0 + py;
                outb[((size_t)(b*256 + oc    )*32 + oy)*32 + lane] = f.x + b0;
                outb[((size_t)(b*256 + oc + 1)*32 + oy)*32 + lane] = f.y + b1;
            }
        }
}

// ---------------- conv1x1 GEMM, f32x2 pixel pairs ---------------------------
template<int CIN, int INMODE, int OUTRELU, int RESMODE>
__global__ void __launch_bounds__(256) k_conv1p(
    const float* __restrict__ in0, const float* __restrict__ in1,
    const float* __restrict__ w, const float* __restrict__ bias,
    const float* __restrict__ res0, const float* __restrict__ res1,
    float* __restrict__ out, float* __restrict__ out2, int cout)
{
    int b  = blockIdx.x >> 3;
    int pt = blockIdx.x & 7;
    int oc0 = blockIdx.y * 64;
    int tx = threadIdx.x, ty = threadIdx.y;
    int tid = ty * 32 + tx;
    int px0 = pt * 128;

    __shared__ __align__(16) float  s_in[16][128];
    __shared__ __align__(16) float2 s_w[64][16];

    u64 acc[8][2] = {};

    for (int c0 = 0; c0 < CIN; c0 += 16) {
        __syncthreads();
        for (int e = tid; e < 512; e += 256) {
            int i = e >> 5, p4 = (e & 31) * 4;
            size_t gi = (size_t)(b*CIN + c0 + i)*1024 + px0 + p4;
            float4 v = *(const float4*)&in0[gi];
            if (INMODE == 2) {
                float4 u = *(const float4*)&in1[gi];
                v.x = fmaxf(v.x + u.x, 0.f); v.y = fmaxf(v.y + u.y, 0.f);
                v.z = fmaxf(v.z + u.z, 0.f); v.w = fmaxf(v.w + u.w, 0.f);
            }
            *(float4*)&s_in[i][p4] = v;
        }
        for (int e = tid; e < 1024; e += 256) {
            int o = e >> 4, i = e & 15;
            float wv = w[(size_t)(oc0 + o)*CIN + c0 + i];
            s_w[o][i] = make_float2(wv, wv);
        }
        __syncthreads();

        #pragma unroll
        for (int i = 0; i < 16; i++) {
            u64 v0 = *(const u64*)&s_in[i][2*tx];
            u64 v1 = *(const u64*)&s_in[i][2*tx + 64];
            #pragma unroll
            for (int j = 0; j < 8; j++) {
                u64 wp = *(const u64*)&s_w[ty*8 + j][i];
                FMA2(acc[j][0], wp, v0);
                FMA2(acc[j][1], wp, v1);
            }
        }
    }

    #pragma unroll
    for (int j = 0; j < 8; j++) {
        int oc = oc0 + ty*8 + j;
        float bv = bias[oc];
        #pragma unroll
        for (int m = 0; m < 2; m++) {
            size_t idx = (size_t)(b*cout + oc)*1024 + px0 + 2*tx + 64*m;
            float2 f = unpack2(acc[j][m]);
            float ax = f.x + bv, ay = f.y + bv;
            if (RESMODE == 1) { ax += res0[idx]; ay += res0[idx + 1]; }
            if (RESMODE == 2) {
                ax += fmaxf(res0[idx]     + res1[idx],     0.f);
                ay += fmaxf(res0[idx + 1] + res1[idx + 1], 0.f);
            }
            if (OUTRELU) { ax = fmaxf(ax, 0.f); ay = fmaxf(ay, 0.f); }
            out[idx] = ax; out[idx + 1] = ay;
            if (out2) { out2[idx] = ax; out2[idx + 1] = ay; }
        }
    }
}

// ---------------- VQ ---------------------------------------------------------
__global__ void k_vq(const float* __restrict__ codebook, float* __restrict__ d_out)
{
    int pos = blockIdx.x * 128 + threadIdx.x;
    int b = pos >> 10, hw = pos & 1023;

    float z[64], z2 = 0.f;
    #pragma unroll
    for (int c = 0; c < 64; c++) {
        z[c] = g_z[(size_t)(b*64 + c)*1024 + hw];
        z2 += z[c]*z[c];
    }

    __shared__ float s_cb[128][64];
    __shared__ float s_n[128];

    float best = INFINITY; int bestk = 0;
    for (int k0 = 0; k0 < 512; k0 += 128) {
        __syncthreads();
        for (int e = threadIdx.x; e < 8192; e += 128)
            s_cb[e >> 6][e & 63] = codebook[k0*64 + e];
        __syncthreads();
        {
            float n = 0.f;
            #pragma unroll
            for (int c = 0; c < 64; c++) { float cv = s_cb[threadIdx.x][c]; n += cv*cv; }
            s_n[threadIdx.x] = n;
        }
        __syncthreads();
        for (int k = 0; k < 128; k++) {
            float dot = 0.f;
            #pragma unroll
            for (int c = 0; c < 64; c++) dot += z[c]*s_cb[k][c];
            float d = (z2 - 2.f*dot) + s_n[k];
            if (d < best) { best = d; bestk = k0 + k; }
        }
    }

    d_out[IDS_OFF + pos] = (float)bestk;
    const float* crow = codebook + (size_t)bestk*64;
    #pragma unroll
    for (int c = 0; c < 64; c++) {
        float v = crow[c];
        size_t idx = (size_t)(b*64 + c)*1024 + hw;
        g_ek[idx] = v;
        d_out[EK_OFF + idx] = v;
    }
}

// ---------------- t1: convT 256->256 k4 s2 p1, 32->64, relu (cp.async db) ---
__global__ void __launch_bounds__(128, 4) k_t1(const float* __restrict__ wT,
                                               const float* __restrict__ bias)
{
    int b   = blockIdx.x >> 4;
    int oy0 = (blockIdx.x & 15) * 4;
    int obk = blockIdx.y;
    int oc0 = obk * 32;
    int tid = threadIdx.x;
    int lane = tid & 31, warp = tid >> 5;
    int ocw = warp * 8;
    int q   = lane & 7;
    int oyl = lane >> 3;
    int oy  = oy0 + oyl;

    int kyA, kyB;
    if (oy & 1) { kyA = 0; kyB = 2; } else { kyA = 1; kyB = 3; }

    __shared__ __align__(16) float2 s_in[2][4][4][2][34];
    __shared__ __align__(16) float  s_w[2][2048];

    u64 accE[2][2][4] = {}, accO[2][2][4] = {};

    #define T1_STAGE_IN(bf, c0) do {                                           \
        _Pragma("unroll")                                                      \
        for (int i = 0; i < 8; i++) {                                          \
            int idx = warp * 8 + i;                                            \
            int c  = idx >> 3;                                                 \
            int ol = (idx >> 1) & 3;                                           \
            int rr = idx & 1;                                                  \
            int o_y = oy0 + ol;                                                \
            int iy;                                                            \
            if (o_y & 1) iy = rr ? ((o_y - 1) >> 1) : ((o_y + 1) >> 1);        \
            else         iy = rr ? ((o_y >> 1) - 1) : (o_y >> 1);              \
            bool yok = (iy >= 0 && iy < 32);                                   \
            const float* row = &g_r[((size_t)(b*256 + (c0) + c)*32 + iy)*32];  \
            int ix = lane - 1;                                                 \
            float v = (yok && ix >= 0) ? row[ix] : 0.f;                        \
            s_in[bf][c][ol][rr][lane] = make_float2(v, v);                     \
            if (lane < 2) {                                                    \
                int ix2 = lane + 31;                                           \
                float v2 = (yok && ix2 < 32) ? row[ix2] : 0.f;                 \
                s_in[bf][c][ol][rr][lane + 32] = make_float2(v2, v2);          \
            }                                                                  \
        }                                                                      \
    } while (0)

    #define T1_STAGE_W(bf, c0) do {                                            \
        const float4* src = (const float4*)(wT + (size_t)obk*131072 + (size_t)(c0)*512); \
        unsigned dst = (unsigned)__cvta_generic_to_shared(s_w[bf]);            \
        _Pragma("unroll")                                                      \
        for (int i = 0; i < 4; i++)                                            \
            cpa16(dst + (tid + 128*i)*16, src + tid + 128*i);                  \
    } while (0)

    T1_STAGE_W(0, 0); CPA_COMMIT();
    T1_STAGE_IN(0, 0);
    CPA_WAIT0();
    __syncthreads();

    int n = 0;
    for (int c0 = 0; c0 < 256; c0 += 4) {
        int nx = c0 + 4;
        if (nx < 256) { T1_STAGE_W(n^1, nx); CPA_COMMIT(); T1_STAGE_IN(n^1, nx); }

        #pragma unroll
        for (int c = 0; c < 4; c++) {
            #pragma unroll
            for (int rr = 0; rr < 2; rr++) {
                int ky = rr ? kyB : kyA;
                u64 v[6];
                #pragma unroll
                for (int i = 0; i < 6; i++)
                    v[i] = *(const u64*)&s_in[n][c][oyl][rr][4*q + i];
                const float* wr0 = &s_w[n][(c*16 + ky*4 + 0)*32 + ocw];
                const float* wr1 = &s_w[n][(c*16 + ky*4 + 1)*32 + ocw];
                const float* wr2 = &s_w[n][(c*16 + ky*4 + 2)*32 + ocw];
                const float* wr3 = &s_w[n][(c*16 + ky*4 + 3)*32 + ocw];
                #pragma unroll
                for (int jj = 0; jj < 2; jj++) {
                    ulonglong2 W0 = *(const ulonglong2*)&wr0[4*jj];
                    ulonglong2 W1 = *(const ulonglong2*)&wr1[4*jj];
                    ulonglong2 W2 = *(const ulonglong2*)&wr2[4*jj];
                    ulonglong2 W3 = *(const ulonglong2*)&wr3[4*jj];
                    #pragma unroll
                    for (int t = 0; t < 4; t++) {
                        FMA2(accE[jj][0][t], W3.x, v[t]);
                        FMA2(accE[jj][0][t], W1.x, v[t + 1]);
                        FMA2(accE[jj][1][t], W3.y, v[t]);
                        FMA2(accE[jj][1][t], W1.y, v[t + 1]);
                        FMA2(accO[jj][0][t], W0.x, v[t + 2]);
                        FMA2(accO[jj][0][t], W2.x, v[t + 1]);
                        FMA2(accO[jj][1][t], W0.y, v[t + 2]);
                        FMA2(accO[jj][1][t], W2.y, v[t + 1]);
                    }
                }
            }
        }
        if (nx < 256) CPA_WAIT0();
        __syncthreads();
        n ^= 1;
    }

    #pragma unroll
    for (int jj = 0; jj < 2; jj++)
        #pragma unroll
        for (int h = 0; h < 2; h++) {
            int oc = oc0 + ocw + 4*jj + 2*h;
            float b0 = bias[oc], b1 = bias[oc + 1];
            #pragma unroll
            for (int t = 0; t < 4; t++) {
                float2 fe = unpack2(accE[jj][h][t]);
                float2 fo = unpack2(accO[jj][h][t]);
                int ox = 8*q + 2*t;
                size_t base0 = ((size_t)(b*256 + oc    )*64 + oy)*64;
                size_t base1 = ((size_t)(b*256 + oc + 1)*64 + oy)*64;
                g_h1[base0 + ox]     = fmaxf(fe.x + b0, 0.f);
                g_h1[base1 + ox]     = fmaxf(fe.y + b1, 0.f);
                g_h1[base0 + ox + 1] = fmaxf(fo.x + b0, 0.f);
                g_h1[base1 + ox + 1] = fmaxf(fo.y + b1, 0.f);
            }
        }
}

// ---------------- t2: convT 256->3 k4 s2 p1, 64->128, sigmoid ---------------
__global__ void __launch_bounds__(128) k_t2(const float* __restrict__ w,
                                            const float* __restrict__ bias,
                                            float* __restrict__ out)
{
    int b  = blockIdx.x >> 6;
    int m  = blockIdx.x & 63;
    int tx = threadIdx.x;
    int ty = threadIdx.y;
    int tid = ty * 64 + tx;
    int oy = 2*m + ty;

    int rowA = ty ? 2 : 1, kyA = ty ? 0 : 1;
    int rowB = ty ? 1 : 0, kyB = ty ? 2 : 3;

    __shared__ float s_in[16][3][66];
    __shared__ float s_w[16][3][16];

    float acc[3][2];
    #pragma unroll
    for (int o = 0; o < 3; o++) { acc[o][0] = 0.f; acc[o][1] = 0.f; }

    for (int c0 = 0; c0 < 256; c0 += 16) {
        __syncthreads();
        for (int e = tid; e < 3168; e += 128) {
            int c = e / 198, rem = e % 198;
            int r = rem / 66, col = rem % 66;
            int iy = m - 1 + r, ix = col - 1;
            float v = 0.f;
            if (iy >= 0 && iy < 64 && ix >= 0 && ix < 64)
                v = g_h1[((size_t)(b*256 + c0 + c)*64 + iy)*64 + ix];
            s_in[c][r][col] = v;
        }
        for (int e = tid; e < 768; e += 128) {
            int c = e / 48, rem = e % 48;
            s_w[c][rem / 16][rem % 16] = w[((size_t)(c0 + c)*3 + rem/16)*16 + rem%16];
        }
        __syncthreads();

        #pragma unroll
        for (int c = 0; c < 16; c++)
            #pragma unroll
            for (int rr = 0; rr < 2; rr++) {
                int row = rr ? rowB : rowA;
                int ky  = rr ? kyB : kyA;
                float a  = s_in[c][row][tx];
                float bb = s_in[c][row][tx + 1];
                float cc = s_in[c][row][tx + 2];
                #pragma unroll
                for (int o = 0; o < 3; o++) {
                    const float* wr = s_w[c][o];
                    acc[o][0] += wr[ky*4 + 3]*a  + wr[ky*4 + 1]*bb;
                    acc[o][1] += wr[ky*4 + 0]*cc + wr[ky*4 + 2]*bb;
                }
            }
    }

    #pragma unroll
    for (int o = 0; o < 3; o++) {
        float bv = bias[o];
        #pragma unroll
        for (int p = 0; p < 2; p++) {
            float v = acc[o][p] + bv;
            out[((size_t)(b*3 + o)*128 + oy)*128 + 2*tx + p] = 1.f / (1.f + expf(-v));
        }
    }
}

// ---------------- launch ----------------------------------------------------
extern "C" void kernel_launch(void* const* d_in, const int* in_sizes, int n_in,
                              void* d_out, int out_size)
{
    const float* x        = (const float*)d_in[0];
    const float* c1_w     = (const float*)d_in[1];
    const float* c1_b     = (const float*)d_in[2];
    const float* c2_w     = (const float*)d_in[3];
    const float* c2_b     = (const float*)d_in[4];
    const float* r0_w3    = (const float*)d_in[5];
    const float* r0_b3    = (const float*)d_in[6];
    const float* r0_w1    = (const float*)d_in[7];
    const float* r0_b1    = (const float*)d_in[8];
    const float* r1_w3    = (const float*)d_in[9];
    const float* r1_b3    = (const float*)d_in[10];
    const float* r1_w1    = (const float*)d_in[11];
    const float* r1_b1    = (const float*)d_in[12];
    const float* to_z_w   = (const float*)d_in[13];
    const float* to_z_b   = (const float*)d_in[14];
    const float* codebook = (const float*)d_in[15];
    const float* from_z_w = (const float*)d_in[16];
    const float* from_z_b = (const float*)d_in[17];
    const float* t1_w     = (const float*)d_in[18];
    const float* t1_b     = (const float*)d_in[19];
    const float* t2_w     = (const float*)d_in[20];
    const float* t2_b     = (const float*)d_in[21];

    float* out = (float*)d_out;

    float *p_h2, *p_r, *p_z, *p_ek, *p_wc2t, *p_w3t0, *p_w3t1, *p_wt1t;
    float *p_p0, *p_p1, *p_rp0, *p_rp1;
    cudaGetSymbolAddress((void**)&p_h2, g_h2);
    cudaGetSymbolAddress((void**)&p_r,  g_r);
    cudaGetSymbolAddress((void**)&p_z,  g_z);
    cudaGetSymbolAddress((void**)&p_ek, g_ek);
    cudaGetSymbolAddress((void**)&p_wc2t, g_wc2t);
    cudaGetSymbolAddress((void**)&p_w3t0, g_w3t0);
    cudaGetSymbolAddress((void**)&p_w3t1, g_w3t1);
    cudaGetSymbolAddress((void**)&p_wt1t, g_wt1t);
    cudaGetSymbolAddress((void**)&p_p0,  g_p0);
    cudaGetSymbolAddress((void**)&p_p1,  g_p1);
    cudaGetSymbolAddress((void**)&p_rp0, g_rp0);
    cudaGetSymbolAddress((void**)&p_rp1, g_rp1);

    // 4th launch = ncu capture slot = k_c2
    k_dummy<<<1, 32>>>();
    trc2<<<dim3(64, 4), dim3(64, 16)>>>(c2_w, p_wc2t);
    k_c1<<<dim3(B*64, 16), dim3(64, 4)>>>(x, c1_w, c1_b);
    k_c2<<<dim3(64, 4, 2), 128>>>(p_wc2t, c2_b, p_p0, p_p1);   // ncu captures this

    tr3<<<dim3(256, 4), dim3(64, 9)>>>(r0_w3, p_w3t0);
    tr3<<<dim3(256, 4), dim3(64, 9)>>>(r1_w3, p_w3t1);
    trt1<<<dim3(32, 8), dim3(32, 16)>>>(t1_w, p_wt1t);

    k_res3<1><<<dim3(64, 4, 2), 128>>>(p_w3t0, r0_b3, p_p0, p_p1, p_rp0, p_rp1);
    k_conv1p<256, 2, 0, 2><<<dim3(B*8, 4), dim3(32, 8)>>>(
        p_rp0, p_rp1, r0_w1, r0_b1, p_p0, p_p1, p_h2, nullptr, 256);

    k_res3<0><<<dim3(64, 4, 2), 128>>>(p_w3t1, r1_b3, p_h2, nullptr, p_rp0, p_rp1);
    k_conv1p<256, 2, 0, 1><<<dim3(B*8, 4), dim3(32, 8)>>>(
        p_rp0, p_rp1, r1_w1, r1_b1, p_h2, nullptr, p_h2, nullptr, 256);

    k_conv1p<256, 0, 0, 0><<<dim3(B*8, 1), dim3(32, 8)>>>(
        p_h2, nullptr, to_z_w, to_z_b, nullptr, nullptr, p_z, out + ZE_OFF, 64);

    k_vq<<<64, 128>>>(codebook, out);

    k_conv1p<64, 0, 1, 0><<<dim3(B*8, 4), dim3(32, 8)>>>(
        p_ek, nullptr, from_z_w, from_z_b, nullptr, nullptr, p_r, nullptr, 256);
    k_t1<<<dim3(128, 8), 128>>>(p_wt1t, t1_b);
    k_t2<<<512, dim3(64, 2)>>>(t2_w, t2_b, out);

    (void)in_sizes; (void)n_in; (void)out_size;
}

// round 12
// speedup vs baseline: 1.0734x; 1.0734x over previous
#include <cuda_runtime.h>
#include <cuda_bf16.h>
#include <math.h>

// VQ-VAE fwd fp32 NCHW. Output: out | z_e | e_k | ids (float32 concat)
#define B 8
#define OUT_N   (8*3*128*128)
#define ZE_OFF  OUT_N
#define ZE_N    (8*64*32*32)
#define EK_OFF  (ZE_OFF + ZE_N)
#define IDS_OFF (EK_OFF + ZE_N)

typedef unsigned long long u64;
#define FMA2(d, a, b) asm("fma.rn.f32x2 %0, %1, %2, %0;" : "+l"(d) : "l"(a), "l"(b))
__device__ __forceinline__ float2 unpack2(u64 v) {
    float2 r; asm("mov.b64 {%0, %1}, %2;" : "=f"(r.x), "=f"(r.y) : "l"(v)); return r;
}
__device__ __forceinline__ void cpa16(unsigned s, const float4* g) {
    asm volatile("cp.async.ca.shared.global [%0], [%1], 16;" :: "r"(s), "l"(g));
}
#define CPA_COMMIT() asm volatile("cp.async.commit_group;" ::: "memory")
#define CPA_WAIT0()  asm volatile("cp.async.wait_group 0;" ::: "memory")

__device__ float g_h1[8u*256u*64u*64u];
__device__ float g_h2[8u*256u*32u*32u];
__device__ float g_r [8u*256u*32u*32u];
__device__ float g_z [8u*64u*32u*32u];
__device__ float g_ek[8u*64u*32u*32u];
// k-split partial buffers
__device__ float g_p0 [8u*256u*32u*32u];
__device__ float g_p1 [8u*256u*32u*32u];
__device__ float g_rp0[8u*256u*32u*32u];
__device__ float g_rp1[8u*256u*32u*32u];

// transposed weight scratch (layouts linear in ic)
__device__ float g_wc2t[4u*64u*4096u];
__device__ float g_w3t0[4u*32u*4608u];
__device__ float g_w3t1[4u*32u*4608u];
__device__ float g_wt1t[8u*32u*4096u];

__global__ void k_dummy() {}

// ---------------- weight transposes (tiny) ----------------------------------
__global__ void tr3(const float* __restrict__ w, float* __restrict__ o_)
{
    int o = threadIdx.x, tap = threadIdx.y;
    int ic = blockIdx.x, obk = blockIdx.y;
    o_[(((size_t)obk*256 + ic)*9 + tap)*64 + o] =
        w[((size_t)(obk*64 + o)*256 + ic)*9 + tap];
}
__global__ void trc2(const float* __restrict__ w, float* __restrict__ o_)
{
    int o = threadIdx.x, tap = threadIdx.y;
    int chunk = blockIdx.x, obk = blockIdx.y;
    #pragma unroll
    for (int ci = 0; ci < 4; ci++)
        o_[(size_t)(obk*64 + chunk)*4096 + (ci*16 + tap)*64 + o] =
            w[((size_t)(obk*64 + o)*256 + chunk*4 + ci)*16 + tap];
}
__global__ void trt1(const float* __restrict__ w, float* __restrict__ o_)
{
    int o = threadIdx.x, tap = threadIdx.y;
    int chunk = blockIdx.x, obk = blockIdx.y;
    #pragma unroll
    for (int ci = 0; ci < 8; ci++)
        o_[(size_t)(obk*32 + chunk)*4096 + (ci*16 + tap)*32 + o] =
            w[((size_t)(chunk*8 + ci)*256 + obk*32 + o)*16 + tap];
}

// ---------------- c1: 3->256 k4 s2 p1, 128->64, relu (small) ----------------
__global__ void k_c1(const float* __restrict__ x, const float* __restrict__ w,
                     const float* __restrict__ bias)
{
    int b  = blockIdx.x >> 6;
    int oy = blockIdx.x & 63;
    int oc0 = blockIdx.y * 16;
    int tx = threadIdx.x, ty = threadIdx.y;
    int tid = ty * 64 + tx;

    __shared__ float s_in[3][4][130];
    __shared__ float s_w[16][48];

    for (int e = tid; e < 3*4*130; e += 256) {
        int c = e / 520, rem = e % 520;
        int ky = rem / 130, col = rem % 130;
        int iy = 2*oy - 1 + ky, ix = col - 1;
        float v = 0.f;
        if (iy >= 0 && iy < 128 && ix >= 0 && ix < 128)
            v = x[((b*3 + c)*128 + iy)*128 + ix];
        s_in[c][ky][col] = v;
    }
    for (int e = tid; e < 768; e += 256)
        s_w[e / 48][e % 48] = w[(oc0 + e/48)*48 + e%48];
    __syncthreads();

    float acc[4] = {0.f, 0.f, 0.f, 0.f};
    #pragma unroll
    for (int c = 0; c < 3; c++)
        #pragma unroll
        for (int ky = 0; ky < 4; ky++)
            #pragma unroll
            for (int kx = 0; kx < 4; kx++) {
                float v = s_in[c][ky][2*tx + kx];
                int r = (c*4 + ky)*4 + kx;
                #pragma unroll
                for (int j = 0; j < 4; j++) acc[j] += s_w[ty*4 + j][r] * v;
            }
    #pragma unroll
    for (int j = 0; j < 4; j++) {
        int oc = oc0 + ty*4 + j;
        g_h1[((size_t)(b*256 + oc)*64 + oy)*64 + tx] = fmaxf(acc[j] + bias[oc], 0.f);
    }
}

// ---------------- c2: k-split partial conv, 64->32 (reg-split staging) ------
// grid (64, 4, 2), block 128.
__global__ void __launch_bounds__(128, 4) k_c2(const float* __restrict__ wT,
                                               const float* __restrict__ bias,
                                               float* __restrict__ o0,
                                               float* __restrict__ o1)
{
    int b   = blockIdx.x >> 3;
    int oy0 = (blockIdx.x & 7) * 4;
    int obk = blockIdx.y;
    int oc0 = obk * 64;
    int z   = blockIdx.z;
    int ic0 = z * 128;
    float* outb = z ? o1 : o0;
    int tid = threadIdx.x;
    int lane = tid & 31, warp = tid >> 5;
    int ocw = warp * 16;

    __shared__ __align__(16) float2 s_in[2][2][10][2][34];
    __shared__ __align__(16) float  s_w[2][2048];

    u64 acc[4][2][4] = {};
    float pv[5][3];

    const int cW = warp & 1;
    const int rB = (warp >> 1) * 5;

    #define C2_LOAD(c0) do {                                                   \
        const float* rowb = &g_h1[(size_t)(b*256 + (c0) + cW)*4096];           \
        _Pragma("unroll")                                                      \
        for (int rr = 0; rr < 5; rr++) {                                       \
            int r = rB + rr;                                                   \
            int iy = 2*oy0 - 1 + r;                                            \
            bool yok = (iy >= 0 && iy < 64);                                   \
            const float* row = rowb + iy*64;                                   \
            pv[rr][0] = (yok && lane >= 1) ? row[lane - 1] : 0.f;              \
            pv[rr][1] = yok ? row[lane + 31] : 0.f;                            \
            pv[rr][2] = (lane < 1 && yok) ? row[lane + 63] : 0.f;              \
        }                                                                      \
    } while (0)

    #define C2_STS(bf) do {                                                    \
        _Pragma("unroll")                                                      \
        for (int rr = 0; rr < 5; rr++) {                                       \
            int r = rB + rr;                                                   \
            int ix = lane - 1;                                                 \
            s_in[bf][cW][r][ix & 1][(ix + (ix & 1)) >> 1] = make_float2(pv[rr][0], pv[rr][0]); \
            int ix2 = lane + 31;                                               \
            s_in[bf][cW][r][ix2 & 1][(ix2 + (ix2 & 1)) >> 1] = make_float2(pv[rr][1], pv[rr][1]); \
            if (lane < 2) {                                                    \
                int ix3 = lane + 63;                                           \
                s_in[bf][cW][r][ix3 & 1][(ix3 + (ix3 & 1)) >> 1] = make_float2(pv[rr][2], pv[rr][2]); \
            }                                                                  \
        }                                                                      \
    } while (0)

    #define C2_STAGE_W(bf, c0) do {                                            \
        const float4* src = (const float4*)(wT + (size_t)obk*262144 + (size_t)(c0)*1024); \
        unsigned dst = (unsigned)__cvta_generic_to_shared(s_w[bf]);            \
        _Pragma("unroll")                                                      \
        for (int i = 0; i < 4; i++)                                            \
            cpa16(dst + (tid + 128*i)*16, src + tid + 128*i);                  \
    } while (0)

    C2_STAGE_W(0, ic0); CPA_COMMIT();
    C2_LOAD(ic0);
    C2_STS(0);
    CPA_WAIT0();
    __syncthreads();

    int n = 0;
    for (int c0 = ic0; c0 < ic0 + 128; c0 += 2) {
        int nx = c0 + 2;
        bool has = nx < ic0 + 128;
        if (has) { C2_STAGE_W(n^1, nx); CPA_COMMIT(); C2_LOAD(nx); }

        #pragma unroll
        for (int c = 0; c < 2; c++) {
            #pragma unroll
            for (int ky = 0; ky < 4; ky++) {
                #pragma unroll
                for (int kx = 0; kx < 4; kx++) {
                    int p = (kx & 1) ^ 1;
                    int j = lane + (kx >> 1);
                    u64 v0 = *(const u64*)&s_in[n][c][0 + ky][p][j];
                    u64 v1 = *(const u64*)&s_in[n][c][2 + ky][p][j];
                    u64 v2 = *(const u64*)&s_in[n][c][4 + ky][p][j];
                    u64 v3 = *(const u64*)&s_in[n][c][6 + ky][p][j];
                    const float* wrow = &s_w[n][(c*16 + ky*4 + kx)*64 + ocw];
                    #pragma unroll
                    for (int jj = 0; jj < 4; jj++) {
                        ulonglong2 wp = *(const ulonglong2*)&wrow[4*jj];
                        FMA2(acc[jj][0][0], wp.x, v0); FMA2(acc[jj][1][0], wp.y, v0);
                        FMA2(acc[jj][0][1], wp.x, v1); FMA2(acc[jj][1][1], wp.y, v1);
                        FMA2(acc[jj][0][2], wp.x, v2); FMA2(acc[jj][1][2], wp.y, v2);
                        FMA2(acc[jj][0][3], wp.x, v3); FMA2(acc[jj][1][3], wp.y, v3);
                    }
                }
            }
        }
        if (has) { C2_STS(n^1); CPA_WAIT0(); }
        __syncthreads();
        n ^= 1;
    }

    #pragma unroll
    for (int jj = 0; jj < 4; jj++)
        #pragma unroll
        for (int h = 0; h < 2; h++) {
            int oc = oc0 + ocw + 4*jj + 2*h;
            float b0 = z ? 0.f : bias[oc];
            float b1 = z ? 0.f : bias[oc + 1];
            #pragma unroll
            for (int py = 0; py < 4; py++) {
                float2 f = unpack2(acc[jj][h][py]);
                int oy = oy0 + py;
                outb[((size_t)(b*256 + oc    )*32 + oy)*32 + lane] = f.x + b0;
                outb[((size_t)(b*256 + oc + 1)*32 + oy)*32 + lane] = f.y + b1;
            }
        }
}

// ---------------- res3: k-split partial conv3x3 (reg-split staging) ---------
template<int SUMIN>
__global__ void __launch_bounds__(128, 4) k_res3(const float* __restrict__ wT,
                                                 const float* __restrict__ bias,
                                                 const float* __restrict__ in0,
                                                 const float* __restrict__ in1,
                                                 float* __restrict__ o0,
                                                 float* __restrict__ o1)
{
    int b   = blockIdx.x >> 3;
    int oy0 = (blockIdx.x & 7) * 4;
    int obk = blockIdx.y;
    int oc0 = obk * 64;
    int z   = blockIdx.z;
    int ic0 = z * 128;
    float* outb = z ? o1 : o0;
    int tid = threadIdx.x;
    int lane = tid & 31, warp = tid >> 5;
    int ocw = warp * 16;

    __shared__ __align__(16) float2 s_in[2][4][6][34];
    __shared__ __align__(16) float  s_w[2][2304];

    u64 acc[4][2][4] = {};
    float pv[6][2];

    #define R3_LOAD(c0) do {                                                   \
        size_t cb = (size_t)(b*256 + (c0) + warp)*1024;                        \
        _Pragma("unroll")                                                      \
        for (int r = 0; r < 6; r++) {                                          \
            int iy = oy0 - 1 + r;                                              \
            bool yok = (iy >= 0 && iy < 32);                                   \
            float v = 0.f;                                                     \
            if (yok && lane >= 1) {                                            \
                v = in0[cb + iy*32 + lane - 1];                                \
                if (SUMIN) v += in1[cb + iy*32 + lane - 1];                    \
                v = fmaxf(v, 0.f);                                             \
            }                                                                  \
            pv[r][0] = v;                                                      \
            float v2 = 0.f;                                                    \
            if (lane < 1 && yok) {                                             \
                v2 = in0[cb + iy*32 + 31];                                     \
                if (SUMIN) v2 += in1[cb + iy*32 + 31];                         \
                v2 = fmaxf(v2, 0.f);                                           \
            }                                                                  \
            pv[r][1] = v2;                                                     \
        }                                                                      \
    } while (0)

    #define R3_STS(bf) do {                                                    \
        _Pragma("unroll")                                                      \
        for (int r = 0; r < 6; r++) {                                          \
            s_in[bf][warp][r][lane] = make_float2(pv[r][0], pv[r][0]);         \
            if (lane < 2)                                                      \
                s_in[bf][warp][r][lane + 32] = make_float2(pv[r][1], pv[r][1]); \
        }                                                                      \
    } while (0)

    #define R3_STAGE_W(bf, c0) do {                                            \
        const float4* src = (const float4*)(wT + (size_t)obk*147456 + (size_t)(c0)*576); \
        unsigned dst = (unsigned)__cvta_generic_to_shared(s_w[bf]);            \
        _Pragma("unroll")                                                      \
        for (int i = 0; i < 4; i++)                                            \
            cpa16(dst + (tid + 128*i)*16, src + tid + 128*i);                  \
        if (tid < 64) cpa16(dst + (tid + 512)*16, src + tid + 512);            \
    } while (0)

    R3_STAGE_W(0, ic0); CPA_COMMIT();
    R3_LOAD(ic0);
    R3_STS(0);
    CPA_WAIT0();
    __syncthreads();

    int n = 0;
    for (int c0 = ic0; c0 < ic0 + 128; c0 += 4) {
        int nx = c0 + 4;
        bool has = nx < ic0 + 128;
        if (has) { R3_STAGE_W(n^1, nx); CPA_COMMIT(); R3_LOAD(nx); }

        #pragma unroll
        for (int c = 0; c < 4; c++) {
            #pragma unroll
            for (int ky = 0; ky < 3; ky++) {
                #pragma unroll
                for (int kx = 0; kx < 3; kx++) {
                    u64 v0 = *(const u64*)&s_in[n][c][0 + ky][lane + kx];
                    u64 v1 = *(const u64*)&s_in[n][c][1 + ky][lane + kx];
                    u64 v2 = *(const u64*)&s_in[n][c][2 + ky][lane + kx];
                    u64 v3 = *(const u64*)&s_in[n][c][3 + ky][lane + kx];
                    const float* wrow = &s_w[n][(c*9 + ky*3 + kx)*64 + ocw];
                    #pragma unroll
                    for (int jj = 0; jj < 4; jj++) {
                        ulonglong2 wp = *(const ulonglong2*)&wrow[4*jj];
                        FMA2(acc[jj][0][0], wp.x, v0); FMA2(acc[jj][1][0], wp.y, v0);
                        FMA2(acc[jj][0][1], wp.x, v1); FMA2(acc[jj][1][1], wp.y, v1);
                        FMA2(acc[jj][0][2], wp.x, v2); FMA2(acc[jj][1][2], wp.y, v2);
                        FMA2(acc[jj][0][3], wp.x, v3); FMA2(acc[jj][1][3], wp.y, v3);
                    }
                }
            }
        }
        if (has) { R3_STS(n^1); CPA_WAIT0(); }
        __syncthreads();
        n ^= 1;
    }

    #pragma unroll
    for (int jj = 0; jj < 4; jj++)
        #pragma unroll
        for (int h = 0; h < 2; h++) {
            int oc = oc0 + ocw + 4*jj + 2*h;
            float b0 = z ? 0.f : bias[oc];
            float b1 = z ? 0.f : bias[oc + 1];
            #pragma unroll
            for (int py = 0; py < 4; py++) {
                float2 f = unpack2(acc[jj][h][py]);
                int oy = oy0 + py;
                outb[((size_t)(b*256 + oc    )*32 + oy)*32 + lane] = f.x + b0;
                outb[((size_t)(b*256 + oc + 1)*32 + oy)*32 + lane] = f.y + b1;
            }
        }
}

// ---------------- conv1x1 GEMM, f32x2 pixel pairs ---------------------------
template<int CIN, int INMODE, int OUTRELU, int RESMODE>
__global__ void __launch_bounds__(256) k_conv1p(
    const float* __restrict__ in0, const float* __restrict__ in1,
    const float* __restrict__ w, const float* __restrict__ bias,
    const float* __restrict__ res0, const float* __restrict__ res1,
    float* __restrict__ out, float* __restrict__ out2, int cout)
{
    int b  = blockIdx.x >> 3;
    int pt = blockIdx.x & 7;
    int oc0 = blockIdx.y * 64;
    int tx = threadIdx.x, ty = threadIdx.y;
    int tid = ty * 32 + tx;
    int px0 = pt * 128;

    __shared__ __align__(16) float  s_in[16][128];
    __shared__ __align__(16) float2 s_w[64][16];

    u64 acc[8][2] = {};

    for (int c0 = 0; c0 < CIN; c0 += 16) {
        __syncthreads();
        for (int e = tid; e < 512; e += 256) {
            int i = e >> 5, p4 = (e & 31) * 4;
            size_t gi = (size_t)(b*CIN + c0 + i)*1024 + px0 + p4;
            float4 v = *(const float4*)&in0[gi];
            if (INMODE == 2) {
                float4 u = *(const float4*)&in1[gi];
                v.x = fmaxf(v.x + u.x, 0.f); v.y = fmaxf(v.y + u.y, 0.f);
                v.z = fmaxf(v.z + u.z, 0.f); v.w = fmaxf(v.w + u.w, 0.f);
            }
            *(float4*)&s_in[i][p4] = v;
        }
        for (int e = tid; e < 1024; e += 256) {
            int o = e >> 4, i = e & 15;
            float wv = w[(size_t)(oc0 + o)*CIN + c0 + i];
            s_w[o][i] = make_float2(wv, wv);
        }
        __syncthreads();

        #pragma unroll
        for (int i = 0; i < 16; i++) {
            u64 v0 = *(const u64*)&s_in[i][2*tx];
            u64 v1 = *(const u64*)&s_in[i][2*tx + 64];
            #pragma unroll
            for (int j = 0; j < 8; j++) {
                u64 wp = *(const u64*)&s_w[ty*8 + j][i];
                FMA2(acc[j][0], wp, v0);
                FMA2(acc[j][1], wp, v1);
            }
        }
    }

    #pragma unroll
    for (int j = 0; j < 8; j++) {
        int oc = oc0 + ty*8 + j;
        float bv = bias[oc];
        #pragma unroll
        for (int m = 0; m < 2; m++) {
            size_t idx = (size_t)(b*cout + oc)*1024 + px0 + 2*tx + 64*m;
            float2 f = unpack2(acc[j][m]);
            float ax = f.x + bv, ay = f.y + bv;
            if (RESMODE == 1) { ax += res0[idx]; ay += res0[idx + 1]; }
            if (RESMODE == 2) {
                ax += fmaxf(res0[idx]     + res1[idx],     0.f);
                ay += fmaxf(res0[idx + 1] + res1[idx + 1], 0.f);
            }
            if (OUTRELU) { ax = fmaxf(ax, 0.f); ay = fmaxf(ay, 0.f); }
            out[idx] = ax; out[idx + 1] = ay;
            if (out2) { out2[idx] = ax; out2[idx + 1] = ay; }
        }
    }
}

// ---------------- VQ ---------------------------------------------------------
__global__ void k_vq(const float* __restrict__ codebook, float* __restrict__ d_out)
{
    int pos = blockIdx.x * 128 + threadIdx.x;
    int b = pos >> 10, hw = pos & 1023;

    float z[64], z2 = 0.f;
    #pragma unroll
    for (int c = 0; c < 64; c++) {
        z[c] = g_z[(size_t)(b*64 + c)*1024 + hw];
        z2 += z[c]*z[c];
    }

    __shared__ float s_cb[128][64];
    __shared__ float s_n[128];

    float best = INFINITY; int bestk = 0;
    for (int k0 = 0; k0 < 512; k0 += 128) {
        __syncthreads();
        for (int e = threadIdx.x; e < 8192; e += 128)
            s_cb[e >> 6][e & 63] = codebook[k0*64 + e];
        __syncthreads();
        {
            float n = 0.f;
            #pragma unroll
            for (int c = 0; c < 64; c++) { float cv = s_cb[threadIdx.x][c]; n += cv*cv; }
            s_n[threadIdx.x] = n;
        }
        __syncthreads();
        for (int k = 0; k < 128; k++) {
            float dot = 0.f;
            #pragma unroll
            for (int c = 0; c < 64; c++) dot += z[c]*s_cb[k][c];
            float d = (z2 - 2.f*dot) + s_n[k];
            if (d < best) { best = d; bestk = k0 + k; }
        }
    }

    d_out[IDS_OFF + pos] = (float)bestk;
    const float* crow = codebook + (size_t)bestk*64;
    #pragma unroll
    for (int c = 0; c < 64; c++) {
        float v = crow[c];
        size_t idx = (size_t)(b*64 + c)*1024 + hw;
        g_ek[idx] = v;
        d_out[EK_OFF + idx] = v;
    }
}

// ---------------- t1: convT 256->256 k4 s2 p1, 32->64 (reg-split staging) ---
__global__ void __launch_bounds__(128, 4) k_t1(const float* __restrict__ wT,
                                               const float* __restrict__ bias)
{
    int b   = blockIdx.x >> 4;
    int oy0 = (blockIdx.x & 15) * 4;
    int obk = blockIdx.y;
    int oc0 = obk * 32;
    int tid = threadIdx.x;
    int lane = tid & 31, warp = tid >> 5;
    int ocw = warp * 8;
    int q   = lane & 7;
    int oyl = lane >> 3;
    int oy  = oy0 + oyl;

    int kyA, kyB;
    if (oy & 1) { kyA = 0; kyB = 2; } else { kyA = 1; kyB = 3; }

    __shared__ __align__(16) float2 s_in[2][4][4][2][34];
    __shared__ __align__(16) float  s_w[2][2048];

    u64 accE[2][2][4] = {}, accO[2][2][4] = {};
    float pv[8][2];

    #define T1_LOAD(c0) do {                                                   \
        _Pragma("unroll")                                                      \
        for (int i = 0; i < 8; i++) {                                          \
            int idx = warp * 8 + i;                                            \
            int c  = idx >> 3;                                                 \
            int ol = (idx >> 1) & 3;                                           \
            int rr = idx & 1;                                                  \
            int o_y = oy0 + ol;                                                \
            int iy;                                                            \
            if (o_y & 1) iy = rr ? ((o_y - 1) >> 1) : ((o_y + 1) >> 1);        \
            else         iy = rr ? ((o_y >> 1) - 1) : (o_y >> 1);              \
            bool yok = (iy >= 0 && iy < 32);                                   \
            const float* row = &g_r[((size_t)(b*256 + (c0) + c)*32 + iy)*32];  \
            pv[i][0] = (yok && lane >= 1) ? row[lane - 1] : 0.f;               \
            pv[i][1] = (lane < 1 && yok) ? row[31] : 0.f;                      \
        }                                                                      \
    } while (0)

    #define T1_STS(bf) do {                                                    \
        _Pragma("unroll")                                                      \
        for (int i = 0; i < 8; i++) {                                          \
            int idx = warp * 8 + i;                                            \
            int c  = idx >> 3;                                                 \
            int ol = (idx >> 1) & 3;                                           \
            int rr = idx & 1;                                                  \
            s_in[bf][c][ol][rr][lane] = make_float2(pv[i][0], pv[i][0]);       \
            if (lane < 2)                                                      \
                s_in[bf][c][ol][rr][lane + 32] = make_float2(pv[i][1], pv[i][1]); \
        }                                                                      \
    } while (0)

    #define T1_STAGE_W(bf, c0) do {                                            \
        const float4* src = (const float4*)(wT + (size_t)obk*131072 + (size_t)(c0)*512); \
        unsigned dst = (unsigned)__cvta_generic_to_shared(s_w[bf]);            \
        _Pragma("unroll")                                                      \
        for (int i = 0; i < 4; i++)                                            \
            cpa16(dst + (tid + 128*i)*16, src + tid + 128*i);                  \
    } while (0)

    T1_STAGE_W(0, 0); CPA_COMMIT();
    T1_LOAD(0);
    T1_STS(0);
    CPA_WAIT0();
    __syncthreads();

    int n = 0;
    for (int c0 = 0; c0 < 256; c0 += 4) {
        int nx = c0 + 4;
        bool has = nx < 256;
        if (has) { T1_STAGE_W(n^1, nx); CPA_COMMIT(); T1_LOAD(nx); }

        #pragma unroll
        for (int c = 0; c < 4; c++) {
            #pragma unroll
            for (int rr = 0; rr < 2; rr++) {
                int ky = rr ? kyB : kyA;
                u64 v[6];
                #pragma unroll
                for (int i = 0; i < 6; i++)
                    v[i] = *(const u64*)&s_in[n][c][oyl][rr][4*q + i];
                const float* wr0 = &s_w[n][(c*16 + ky*4 + 0)*32 + ocw];
                const float* wr1 = &s_w[n][(c*16 + ky*4 + 1)*32 + ocw];
                const float* wr2 = &s_w[n][(c*16 + ky*4 + 2)*32 + ocw];
                const float* wr3 = &s_w[n][(c*16 + ky*4 + 3)*32 + ocw];
                #pragma unroll
                for (int jj = 0; jj < 2; jj++) {
                    ulonglong2 W0 = *(const ulonglong2*)&wr0[4*jj];
                    ulonglong2 W1 = *(const ulonglong2*)&wr1[4*jj];
                    ulonglong2 W2 = *(const ulonglong2*)&wr2[4*jj];
                    ulonglong2 W3 = *(const ulonglong2*)&wr3[4*jj];
                    #pragma unroll
                    for (int t = 0; t < 4; t++) {
                        FMA2(accE[jj][0][t], W3.x, v[t]);
                        FMA2(accE[jj][0][t], W1.x, v[t + 1]);
                        FMA2(accE[jj][1][t], W3.y, v[t]);
                        FMA2(accE[jj][1][t], W1.y, v[t + 1]);
                        FMA2(accO[jj][0][t], W0.x, v[t + 2]);
                        FMA2(accO[jj][0][t], W2.x, v[t + 1]);
                        FMA2(accO[jj][1][t], W0.y, v[t + 2]);
                        FMA2(accO[jj][1][t], W2.y, v[t + 1]);
                    }
                }
            }
        }
        if (has) { T1_STS(n^1); CPA_WAIT0(); }
        __syncthreads();
        n ^= 1;
    }

    #pragma unroll
    for (int jj = 0; jj < 2; jj++)
        #pragma unroll
        for (int h = 0; h < 2; h++) {
            int oc = oc0 + ocw + 4*jj + 2*h;
            float b0 = bias[oc], b1 = bias[oc + 1];
            #pragma unroll
            for (int t = 0; t < 4; t++) {
                float2 fe = unpack2(accE[jj][h][t]);
                float2 fo = unpack2(accO[jj][h][t]);
                int ox = 8*q + 2*t;
                size_t base0 = ((size_t)(b*256 + oc    )*64 + oy)*64;
                size_t base1 = ((size_t)(b*256 + oc + 1)*64 + oy)*64;
                g_h1[base0 + ox]     = fmaxf(fe.x + b0, 0.f);
                g_h1[base1 + ox]     = fmaxf(fe.y + b1, 0.f);
                g_h1[base0 + ox + 1] = fmaxf(fo.x + b0, 0.f);
                g_h1[base1 + ox + 1] = fmaxf(fo.y + b1, 0.f);
            }
        }
}

// ---------------- t2: convT 256->3 k4 s2 p1, 64->128, sigmoid ---------------
__global__ void __launch_bounds__(128) k_t2(const float* __restrict__ w,
                                            const float* __restrict__ bias,
                                            float* __restrict__ out)
{
    int b  = blockIdx.x >> 6;
    int m  = blockIdx.x & 63;
    int tx = threadIdx.x;
    int ty = threadIdx.y;
    int tid = ty * 64 + tx;
    int oy = 2*m + ty;

    int rowA = ty ? 2 : 1, kyA = ty ? 0 : 1;
    int rowB = ty ? 1 : 0, kyB = ty ? 2 : 3;

    __shared__ float s_in[16][3][66];
    __shared__ float s_w[16][3][16];

    float acc[3][2];
    #pragma unroll
    for (int o = 0; o < 3; o++) { acc[o][0] = 0.f; acc[o][1] = 0.f; }

    for (int c0 = 0; c0 < 256; c0 += 16) {
        __syncthreads();
        for (int e = tid; e < 3168; e += 128) {
            int c = e / 198, rem = e % 198;
            int r = rem / 66, col = rem % 66;
            int iy = m - 1 + r, ix = col - 1;
            float v = 0.f;
            if (iy >= 0 && iy < 64 && ix >= 0 && ix < 64)
                v = g_h1[((size_t)(b*256 + c0 + c)*64 + iy)*64 + ix];
            s_in[c][r][col] = v;
        }
        for (int e = tid; e < 768; e += 128) {
            int c = e / 48, rem = e % 48;
            s_w[c][rem / 16][rem % 16] = w[((size_t)(c0 + c)*3 + rem/16)*16 + rem%16];
        }
        __syncthreads();

        #pragma unroll
        for (int c = 0; c < 16; c++)
            #pragma unroll
            for (int rr = 0; rr < 2; rr++) {
                int row = rr ? rowB : rowA;
                int ky  = rr ? kyB : kyA;
                float a  = s_in[c][row][tx];
                float bb = s_in[c][row][tx + 1];
                float cc = s_in[c][row][tx + 2];
                #pragma unroll
                for (int o = 0; o < 3; o++) {
                    const float* wr = s_w[c][o];
                    acc[o][0] += wr[ky*4 + 3]*a  + wr[ky*4 + 1]*bb;
                    acc[o][1] += wr[ky*4 + 0]*cc + wr[ky*4 + 2]*bb;
                }
            }
    }

    #pragma unroll
    for (int o = 0; o < 3; o++) {
        float bv = bias[o];
        #pragma unroll
        for (int p = 0; p < 2; p++) {
            float v = acc[o][p] + bv;
            out[((size_t)(b*3 + o)*128 + oy)*128 + 2*tx + p] = 1.f / (1.f + expf(-v));
        }
    }
}

// ---------------- launch ----------------------------------------------------
extern "C" void kernel_launch(void* const* d_in, const int* in_sizes, int n_in,
                              void* d_out, int out_size)
{
    const float* x        = (const float*)d_in[0];
    const float* c1_w     = (const float*)d_in[1];
    const float* c1_b     = (const float*)d_in[2];
    const float* c2_w     = (const float*)d_in[3];
    const float* c2_b     = (const float*)d_in[4];
    const float* r0_w3    = (const float*)d_in[5];
    const float* r0_b3    = (const float*)d_in[6];
    const float* r0_w1    = (const float*)d_in[7];
    const float* r0_b1    = (const float*)d_in[8];
    const float* r1_w3    = (const float*)d_in[9];
    const float* r1_b3    = (const float*)d_in[10];
    const float* r1_w1    = (const float*)d_in[11];
    const float* r1_b1    = (const float*)d_in[12];
    const float* to_z_w   = (const float*)d_in[13];
    const float* to_z_b   = (const float*)d_in[14];
    const float* codebook = (const float*)d_in[15];
    const float* from_z_w = (const float*)d_in[16];
    const float* from_z_b = (const float*)d_in[17];
    const float* t1_w     = (const float*)d_in[18];
    const float* t1_b     = (const float*)d_in[19];
    const float* t2_w     = (const float*)d_in[20];
    const float* t2_b     = (const float*)d_in[21];

    float* out = (float*)d_out;

    float *p_h2, *p_r, *p_z, *p_ek, *p_wc2t, *p_w3t0, *p_w3t1, *p_wt1t;
    float *p_p0, *p_p1, *p_rp0, *p_rp1;
    cudaGetSymbolAddress((void**)&p_h2, g_h2);
    cudaGetSymbolAddress((void**)&p_r,  g_r);
    cudaGetSymbolAddress((void**)&p_z,  g_z);
    cudaGetSymbolAddress((void**)&p_ek, g_ek);
    cudaGetSymbolAddress((void**)&p_wc2t, g_wc2t);
    cudaGetSymbolAddress((void**)&p_w3t0, g_w3t0);
    cudaGetSymbolAddress((void**)&p_w3t1, g_w3t1);
    cudaGetSymbolAddress((void**)&p_wt1t, g_wt1t);
    cudaGetSymbolAddress((void**)&p_p0,  g_p0);
    cudaGetSymbolAddress((void**)&p_p1,  g_p1);
    cudaGetSymbolAddress((void**)&p_rp0, g_rp0);
    cudaGetSymbolAddress((void**)&p_rp1, g_rp1);

    // 4th launch = ncu capture slot = k_c2
    k_dummy<<<1, 32>>>();
    trc2<<<dim3(64, 4), dim3(64, 16)>>>(c2_w, p_wc2t);
    k_c1<<<dim3(B*64, 16), dim3(64, 4)>>>(x, c1_w, c1_b);
    k_c2<<<dim3(64, 4, 2), 128>>>(p_wc2t, c2_b, p_p0, p_p1);   // ncu captures this

    tr3<<<dim3(256, 4), dim3(64, 9)>>>(r0_w3, p_w3t0);
    tr3<<<dim3(256, 4), dim3(64, 9)>>>(r1_w3, p_w3t1);
    trt1<<<dim3(32, 8), dim3(32, 16)>>>(t1_w, p_wt1t);

    k_res3<1><<<dim3(64, 4, 2), 128>>>(p_w3t0, r0_b3, p_p0, p_p1, p_rp0, p_rp1);
    k_conv1p<256, 2, 0, 2><<<dim3(B*8, 4), dim3(32, 8)>>>(
        p_rp0, p_rp1, r0_w1, r0_b1, p_p0, p_p1, p_h2, nullptr, 256);

    k_res3<0><<<dim3(64, 4, 2), 128>>>(p_w3t1, r1_b3, p_h2, nullptr, p_rp0, p_rp1);
    k_conv1p<256, 2, 0, 1><<<dim3(B*8, 4), dim3(32, 8)>>>(
        p_rp0, p_rp1, r1_w1, r1_b1, p_h2, nullptr, p_h2, nullptr, 256);

    k_conv1p<256, 0, 0, 0><<<dim3(B*8, 1), dim3(32, 8)>>>(
        p_h2, nullptr, to_z_w, to_z_b, nullptr, nullptr, p_z, out + ZE_OFF, 64);

    k_vq<<<64, 128>>>(codebook, out);

    k_conv1p<64, 0, 1, 0><<<dim3(B*8, 4), dim3(32, 8)>>>(
        p_ek, nullptr, from_z_w, from_z_b, nullptr, nullptr, p_r, nullptr, 256);
    k_t1<<<dim3(128, 8), 128>>>(p_wt1t, t1_b);
    k_t2<<<512, dim3(64, 2)>>>(t2_w, t2_b, out);

    (void)in_sizes; (void)n_in; (void)out_size;
}